// round 5
// baseline (speedup 1.0000x reference)
#include <cuda_runtime.h>
#include <cstdint>
#include <cstddef>

// Problem constants
#define TT   512
#define BSZ  64
#define IC_  512
#define HC_  512
#define ZC_  2048
#define MR   (TT*BSZ)

#define RK_CTAS 128
#define RK_THR  256

typedef unsigned long long ull;

// ---------------------------------------------------------------------------
// Static device scratch (no cudaMalloc allowed)
// ---------------------------------------------------------------------------
// z stored TRANSPOSED per step: g_z[((t*2048) + n) * 64 + b]
__device__ float g_z[(size_t)MR * ZC_];        // 256 MB
__device__ float g_hseq[(size_t)MR * HC_];     // 64 MB: layer-0 h sequence [m][512]
__device__ float g_hbuf[2][HC_ * BSZ];         // double-buffered h, TRANSPOSED [j][b]
__device__ unsigned g_barcnt = 0;
__device__ volatile unsigned g_bargen = 0;

// ---------------------------------------------------------------------------
// f32x2 helpers (Blackwell packed fp32 FMA — SASS FFMA2)
// ---------------------------------------------------------------------------
__device__ __forceinline__ ull pack2(float x, float y) {
    ull r; asm("mov.b64 %0, {%1, %2};" : "=l"(r) : "f"(x), "f"(y)); return r;
}
__device__ __forceinline__ void unpack2(ull v, float& x, float& y) {
    asm("mov.b64 {%0, %1}, %2;" : "=f"(x), "=f"(y) : "l"(v));
}
__device__ __forceinline__ void ffma2(ull& d, ull a, ull b) {
    asm("fma.rn.f32x2 %0, %1, %2, %0;" : "+l"(d) : "l"(a), "l"(b));
}

__device__ __forceinline__ float sigf(float x) { return 1.0f / (1.0f + __expf(-x)); }
__device__ __forceinline__ float tanh_fast(float x) {
    float ax = fabsf(x);
    float e = __expf(-2.0f * ax);
    float r = (1.0f - e) / (1.0f + e);
    return copysignf(r, x);
}

// Software grid barrier: 128 CTAs co-resident, with poll backoff.
__device__ __forceinline__ void gbar() {
    __syncthreads();
    if (threadIdx.x == 0) {
        __threadfence();
        unsigned gen = g_bargen;
        if (atomicAdd(&g_barcnt, 1u) == RK_CTAS - 1) {
            g_barcnt = 0;
            __threadfence();
            g_bargen = gen + 1;
        } else {
            while (g_bargen == gen) { __nanosleep(16); }
        }
        __threadfence();
    }
    __syncthreads();
}

// ---------------------------------------------------------------------------
// Phase 1: Zt[t][n][b] = (A @ W[0:512,:] + bias) transposed per step.
// Tile M=128 (2 t x 64 b), N=128, BK=16, 256 threads, per-thread 8x8 via FFMA2.
// Thread map: tx = tid&15 -> m-quads (4tx..4tx+3, +64), ty = tid>>4 -> n octet.
// Epilogue writes float4 along b (coalesced) into transposed layout.
// 2-stage register prefetch pipelines global loads behind compute.
// ---------------------------------------------------------------------------
#define AS_STRIDE 264   // floats per k-row (256 dup'd data + 8 pad)
#define BS_STRIDE 136   // floats per k-row (128 data + 8 pad)

__global__ __launch_bounds__(256) void sgemm_bias_t(
        const float* __restrict__ A,       // [32768, 512] row-major
        const float* __restrict__ W,       // rows 0..511 of [.,2048]
        const float* __restrict__ bias,    // [2048]
        float* __restrict__ Zt) {          // [T][2048][64]
    __shared__ float As2[16 * AS_STRIDE];
    __shared__ float Bs[16 * BS_STRIDE];

    const int tid = threadIdx.x;
    const int m0 = blockIdx.y * 128;
    const int n0 = blockIdx.x * 128;
    const int t0 = blockIdx.y * 2;
    const int tx = tid & 15;        // m quad
    const int ty = tid >> 4;        // n octet

    ull acc[8][4];
#pragma unroll
    for (int i = 0; i < 8; i++)
#pragma unroll
        for (int j = 0; j < 4; j++) acc[i][j] = 0ull;

    const int ar = tid >> 2, ac4 = tid & 3;     // A staging
    const int br = tid >> 5, bc4 = tid & 31;    // B staging

    // Prologue: load tile k0=0 into registers
    float4 aPf[2], bPf[2];
#pragma unroll
    for (int p = 0; p < 2; p++)
        aPf[p] = *(const float4*)(A + (size_t)(m0 + ar + p * 64) * 512 + ac4 * 4);
#pragma unroll
    for (int p = 0; p < 2; p++)
        bPf[p] = *(const float4*)(W + (size_t)(br + p * 8) * ZC_ + n0 + bc4 * 4);

    for (int k0 = 0; k0 < 512; k0 += 16) {
        // Stage registers -> smem (A duplicated)
#pragma unroll
        for (int p = 0; p < 2; p++) {
            int r = ar + p * 64;
            const float* vf = (const float*)&aPf[p];
#pragma unroll
            for (int q = 0; q < 4; q++) {
                As2[(ac4 * 4 + q) * AS_STRIDE + 2 * r]     = vf[q];
                As2[(ac4 * 4 + q) * AS_STRIDE + 2 * r + 1] = vf[q];
            }
        }
#pragma unroll
        for (int p = 0; p < 2; p++)
            *(float4*)&Bs[(br + p * 8) * BS_STRIDE + bc4 * 4] = bPf[p];
        __syncthreads();

        // Prefetch next tile (latency overlapped with compute below)
        if (k0 + 16 < 512) {
#pragma unroll
            for (int p = 0; p < 2; p++)
                aPf[p] = *(const float4*)(A + (size_t)(m0 + ar + p * 64) * 512 + k0 + 16 + ac4 * 4);
#pragma unroll
            for (int p = 0; p < 2; p++)
                bPf[p] = *(const float4*)(W + (size_t)(k0 + 16 + br + p * 8) * ZC_ + n0 + bc4 * 4);
        }

#pragma unroll
        for (int kk = 0; kk < 16; kk++) {
            ull a[8], b[4];
            {
                const ulonglong2* ap = (const ulonglong2*)&As2[kk * AS_STRIDE + 8 * tx];
                ulonglong2 a01 = ap[0], a23 = ap[1];
                a[0] = a01.x; a[1] = a01.y; a[2] = a23.x; a[3] = a23.y;
                const ulonglong2* ap2 = (const ulonglong2*)&As2[kk * AS_STRIDE + 128 + 8 * tx];
                ulonglong2 a45 = ap2[0], a67 = ap2[1];
                a[4] = a45.x; a[5] = a45.y; a[6] = a67.x; a[7] = a67.y;
            }
            {
                const ulonglong2* bp = (const ulonglong2*)&Bs[kk * BS_STRIDE + 8 * ty];
                ulonglong2 b01 = bp[0], b23 = bp[1];
                b[0] = b01.x; b[1] = b01.y; b[2] = b23.x; b[3] = b23.y;
            }
#pragma unroll
            for (int i = 0; i < 8; i++)
#pragma unroll
                for (int j = 0; j < 4; j++)
                    ffma2(acc[i][j], a[i], b[j]);
        }
        __syncthreads();
    }

    // Epilogue: transposed store, float4 along b, coalesced.
    float bias8[8];
    *(float4*)&bias8[0] = *(const float4*)(bias + n0 + 8 * ty);
    *(float4*)&bias8[4] = *(const float4*)(bias + n0 + 8 * ty + 4);

#pragma unroll
    for (int j = 0; j < 4; j++) {
        int n_e = n0 + 8 * ty + 2 * j;
        float be = bias8[2 * j], bo = bias8[2 * j + 1];
        float lo[8], hi[8];
#pragma unroll
        for (int i = 0; i < 8; i++) unpack2(acc[i][j], lo[i], hi[i]);

        // t-half 0 (b = 4tx..4tx+3)
        *(float4*)(Zt + ((size_t)t0 * ZC_ + n_e) * 64 + 4 * tx) =
            make_float4(lo[0] + be, lo[1] + be, lo[2] + be, lo[3] + be);
        *(float4*)(Zt + ((size_t)t0 * ZC_ + n_e + 1) * 64 + 4 * tx) =
            make_float4(hi[0] + bo, hi[1] + bo, hi[2] + bo, hi[3] + bo);
        // t-half 1
        *(float4*)(Zt + ((size_t)(t0 + 1) * ZC_ + n_e) * 64 + 4 * tx) =
            make_float4(lo[4] + be, lo[5] + be, lo[6] + be, lo[7] + be);
        *(float4*)(Zt + ((size_t)(t0 + 1) * ZC_ + n_e + 1) * 64 + 4 * tx) =
            make_float4(hi[4] + bo, hi[5] + bo, hi[6] + bo, hi[7] + bo);
    }
}

// ---------------------------------------------------------------------------
// Phase 2: persistent recurrence. 128 CTAs x 256 threads (8 warps).
// CTA owns 4 h-columns. Warp w: kq = w>>1 (k sub-split), bh = w&1 (batch half).
// h staged per step in 4 double-buffered 32KB smem chunks (coalesced LDG.128.cg,
// MLP 8, overlapped with compute). Inner loop: smem-only reads + FFMA2.
// Dynamic smem: W 32KB + 2x32KB h + 16KB reduce = 112KB.
// ---------------------------------------------------------------------------
__global__ __launch_bounds__(RK_THR, 1) void lstm_rec(
        const float* __restrict__ Wh,     // [512, 2048] recurrent rows of W
        const float* __restrict__ h0l,    // [512]
        const float* __restrict__ c0l,    // [512]
        float* __restrict__ hseq,         // [T*BS*HC], layout [m][512]
        float* __restrict__ hs_out,       // [BS*HC]
        float* __restrict__ cs_out) {     // [BS*HC]
    extern __shared__ float smem[];
    float* Wsm = smem;                    // [512][16]: 8192 floats
    float* Hs0 = smem + 8192;             // chunk buffer A: 8192 floats (128k x 64b)
    float* Hs1 = smem + 16384;            // chunk buffer B
    ull*   Rsm = (ull*)(smem + 24576);    // [8][4][64] ull partials

    const int tid  = threadIdx.x;
    const int cid  = blockIdx.x;
    const int j0   = cid << 2;
    const int wid  = tid >> 5, lane = tid & 31;
    const int kq   = wid >> 1, bh = wid & 1;
    const int bb   = (bh << 5) + lane;    // batch row for GEMM

    // Weights: Wsm[k*16 + c*4 + g] = Wh[k][g*512 + j0 + c]
    for (int idx = tid; idx < HC_ * 16; idx += RK_THR) {
        int k = idx >> 4, c = (idx >> 2) & 3, g = idx & 3;
        Wsm[idx] = Wh[(size_t)k * ZC_ + (size_t)g * HC_ + j0 + c];
    }

    // Finalizer identity: thread -> (col fc, batch fb)
    const int fc = tid >> 6;
    const int fb = tid & 63;
    const int fj = j0 + fc;
    float cstate = c0l[fj];
    float hlast  = h0l[fj];
    g_hbuf[0][fj * BSZ + fb] = hlast;
    gbar();

    int cur = 0;
    for (int t = 0; t < TT; t++) {
        // z loads (transposed layout -> coalesced); consumed after reduction
        const float* zr = g_z + ((size_t)t * ZC_ + fj) * BSZ + fb;
        float z0 = __ldcg(zr);
        float z1 = __ldcg(zr + HC_ * BSZ);
        float z2 = __ldcg(zr + 2 * HC_ * BSZ);
        float z3 = __ldcg(zr + 3 * HC_ * BSZ);

        const float* hb = g_hbuf[cur];
        ull acc[4][2];
#pragma unroll
        for (int c = 0; c < 4; c++) { acc[c][0] = 0ull; acc[c][1] = 0ull; }

        // Prefetch chunk 0 (32KB, coalesced, MLP 8)
        float4 pf[8];
#pragma unroll
        for (int p = 0; p < 8; p++)
            pf[p] = __ldcg((const float4*)(hb + (size_t)(tid + p * 256) * 4));

#pragma unroll 1
        for (int c = 0; c < 4; c++) {
            float* H = (c & 1) ? Hs1 : Hs0;
            __syncthreads();              // buffer free (prev compute done)
#pragma unroll
            for (int p = 0; p < 8; p++)
                *(float4*)(H + (size_t)(tid + p * 256) * 4) = pf[p];
            __syncthreads();              // data visible
            if (c < 3) {
                const float* nb = hb + (size_t)(c + 1) * 8192;
#pragma unroll
                for (int p = 0; p < 8; p++)
                    pf[p] = __ldcg((const float4*)(nb + (size_t)(tid + p * 256) * 4));
            }
            // Compute: warp handles k_local in [kq*32, kq*32+32) of this chunk
            const float* Hw = H + (kq << 5) * BSZ;
            const float* Wc = Wsm + ((c << 7) + (kq << 5)) * 16;
#pragma unroll 8
            for (int kk = 0; kk < 32; kk++) {
                float hv = Hw[kk * BSZ + bb];
                ull h2 = pack2(hv, hv);
                const float* wrow = Wc + kk * 16;
#pragma unroll
                for (int cc = 0; cc < 4; cc++) {
                    ulonglong2 w2 = *(const ulonglong2*)(wrow + cc * 4);
                    ffma2(acc[cc][0], h2, w2.x);
                    ffma2(acc[cc][1], h2, w2.y);
                }
            }
        }

        // Cross-warp k-reduction via smem
#pragma unroll
        for (int c = 0; c < 4; c++)
#pragma unroll
            for (int p = 0; p < 2; p++)
                Rsm[((c * 2 + p) * 4 + kq) * 64 + bb] = acc[c][p];
        __syncthreads();

        float f = z0, i = z1, o = z2, g = z3;
#pragma unroll
        for (int q = 0; q < 4; q++) {
            float a0, a1, a2, a3;
            unpack2(Rsm[((fc * 2 + 0) * 4 + q) * 64 + fb], a0, a1);
            unpack2(Rsm[((fc * 2 + 1) * 4 + q) * 64 + fb], a2, a3);
            f += a0; i += a1; o += a2; g += a3;
        }
        f = sigf(f + 1.0f);           // FORGET_BIAS
        i = sigf(i);
        o = sigf(o);
        g = tanh_fast(g);
        cstate = cstate * f + g * i;
        hlast = o * tanh_fast(cstate);

        int nxt = cur ^ 1;
        __stcg(&g_hbuf[nxt][fj * BSZ + fb], hlast);
        hseq[(size_t)(t * BSZ + fb) * HC_ + fj] = hlast;
        gbar();
        cur = nxt;
    }

    hs_out[fb * HC_ + fj] = hlast;
    cs_out[fb * HC_ + fj] = cstate;
}

#define RK_SMEM (112 * 1024)

// ---------------------------------------------------------------------------
// Launch: sgemm(L0) -> rec(L0) -> sgemm(L1) -> rec(L1 -> d_out)
// ---------------------------------------------------------------------------
extern "C" void kernel_launch(void* const* d_in, const int* in_sizes, int n_in,
                              void* d_out, int out_size) {
    const float* x  = (const float*)d_in[0];
    const float* W0 = (const float*)d_in[1];
    const float* b0 = (const float*)d_in[2];
    const float* W1 = (const float*)d_in[3];
    const float* b1 = (const float*)d_in[4];
    const float* h0 = (const float*)d_in[5];
    const float* c0 = (const float*)d_in[6];

    float* out = (float*)d_out;                      // [T, BS, HC]
    float* hs  = out + (size_t)TT * BSZ * HC_;       // [L, BS, HC]
    float* cs  = hs + (size_t)2 * BSZ * HC_;         // [L, BS, HC]

    float* zptr = nullptr;
    float* hseq0 = nullptr;
    cudaGetSymbolAddress((void**)&zptr, g_z);
    cudaGetSymbolAddress((void**)&hseq0, g_hseq);

    static int smem_set = 0;
    if (!smem_set) {
        cudaFuncSetAttribute(lstm_rec, cudaFuncAttributeMaxDynamicSharedMemorySize, RK_SMEM);
        smem_set = 1;
    }

    dim3 ggrid(ZC_ / 128, MR / 128);

    // Layer 0
    sgemm_bias_t<<<ggrid, 256>>>(x, W0, b0, zptr);
    lstm_rec<<<RK_CTAS, RK_THR, RK_SMEM>>>(W0 + (size_t)IC_ * ZC_, h0, c0,
                                           hseq0, hs, cs);
    // Layer 1
    sgemm_bias_t<<<ggrid, 256>>>(hseq0, W1, b1, zptr);
    lstm_rec<<<RK_CTAS, RK_THR, RK_SMEM>>>(W1 + (size_t)HC_ * ZC_, h0 + HC_, c0 + HC_,
                                           out, hs + BSZ * HC_, cs + BSZ * HC_);
}